// round 10
// baseline (speedup 1.0000x reference)
#include <cuda_runtime.h>
#include <cuda_bf16.h>
#include <math.h>

#define NN 50000
#define NE 800000
#define D1 128
#define D2 32

// ---------------- scratch (device globals; no allocations) ----------------
__device__ __align__(16) float g_Wh1[(size_t)NN * D1];
__device__ __align__(16) float g_Wh2[(size_t)NN * D2];
__device__ float g_es1[NN], g_ed1[NN];
__device__ float g_es2[NN], g_ed2[NN];
__device__ int   g_deg[NN];          // histogram, then scatter cursor
__device__ int   g_rowstart[NN + 1];
__device__ int   g_csrc[NE];         // CSR: src node per slot (dst-sorted)

// ================= CSR build (per launch; topology shared by layers) ======
__global__ void k_zero_deg() {
    int i = blockIdx.x * blockDim.x + threadIdx.x;
    if (i < NN) g_deg[i] = 0;
}

__global__ void k_hist(const int* __restrict__ dst) {
    int e = blockIdx.x * blockDim.x + threadIdx.x;
    if (e < NE) atomicAdd(&g_deg[dst[e]], 1);
}

// single-block exclusive scan of g_deg -> g_rowstart; re-zeroes g_deg (cursor)
__global__ void k_scan() {
    const int T = 1024;
    const int CH = (NN + T - 1) / T;  // 49
    int t = threadIdx.x;
    int base = t * CH;

    int s = 0;
    for (int i = 0; i < CH; i++) {
        int idx = base + i;
        if (idx < NN) s += g_deg[idx];
    }
    __shared__ int warpsum[32];
    int lane = t & 31, w = t >> 5;
    int incl = s;
#pragma unroll
    for (int o = 1; o < 32; o <<= 1) {
        int v = __shfl_up_sync(0xffffffffu, incl, o);
        if (lane >= o) incl += v;
    }
    if (lane == 31) warpsum[w] = incl;
    __syncthreads();
    if (w == 0) {
        int v = warpsum[lane];
#pragma unroll
        for (int o = 1; o < 32; o <<= 1) {
            int u = __shfl_up_sync(0xffffffffu, v, o);
            if (lane >= o) v += u;
        }
        warpsum[lane] = v;
    }
    __syncthreads();
    int excl = incl - s + ((w > 0) ? warpsum[w - 1] : 0);

    int run = excl;
    for (int i = 0; i < CH; i++) {
        int idx = base + i;
        if (idx < NN) {
            g_rowstart[idx] = run;
            run += g_deg[idx];
            g_deg[idx] = 0;  // becomes scatter cursor
        }
    }
    if (t == T - 1) g_rowstart[NN] = run;
}

__global__ void k_scatter(const int* __restrict__ src,
                          const int* __restrict__ dst) {
    int e = blockIdx.x * blockDim.x + threadIdx.x;
    if (e >= NE) return;
    int d = dst[e];
    int pos = g_rowstart[d] + atomicAdd(&g_deg[d], 1);
    g_csrc[pos] = src[e];
}

// ================= layer 1 node: Wh1 = x @ W1, es1/ed1 ====================
__global__ void k_node1(const float* __restrict__ x,
                        const float* __restrict__ W1,
                        const float* __restrict__ a1) {
    __shared__ float sW[8 * D1];
    __shared__ float sa[2 * D1];
    int tid = threadIdx.x;
    for (int i = tid; i < 8 * D1; i += blockDim.x) sW[i] = W1[i];
    for (int i = tid; i < 2 * D1; i += blockDim.x) sa[i] = a1[i];
    __syncthreads();

    int warp = tid >> 5, lane = tid & 31;
    int node = blockIdx.x * (blockDim.x >> 5) + warp;
    if (node >= NN) return;

    float xr[8];
#pragma unroll
    for (int k = 0; k < 8; k++) xr[k] = x[node * 8 + k];

    float es = 0.f, ed = 0.f;
#pragma unroll
    for (int i = 0; i < 4; i++) {
        int j = i * 32 + lane;
        float acc = 0.f;
#pragma unroll
        for (int k = 0; k < 8; k++) acc += xr[k] * sW[k * D1 + j];
        g_Wh1[(size_t)node * D1 + j] = acc;
        es += acc * sa[j];
        ed += acc * sa[D1 + j];
    }
#pragma unroll
    for (int o = 16; o; o >>= 1) {
        es += __shfl_down_sync(0xffffffffu, es, o);
        ed += __shfl_down_sync(0xffffffffu, ed, o);
    }
    if (lane == 0) {
        g_es1[node] = es;
        g_ed1[node] = ed;
    }
}

// edge weight: exp(leaky_relu(logit)). Global max-shift dropped: it enters
// only through the +1e-9 denominator term (rel effect ~1e-10 here).
__device__ __forceinline__ float edge_w(float lg) {
    float v = (lg > 0.f) ? lg : 0.2f * lg;
    return __expf(v);
}

// ====== fused: chunked gather layer1 (D=128) + elu + node2 matvec =========
__global__ void k_gagg1_node2(const float* __restrict__ W2,
                              const float* __restrict__ a2) {
    __shared__ float sW[D1 * D2];   // 16 KB
    __shared__ float sa[2 * D2];
    __shared__ float sh[8][D1];     // per-warp out1 row
    int tid = threadIdx.x;
    for (int i = tid; i < D1 * D2; i += blockDim.x) sW[i] = W2[i];
    for (int i = tid; i < 2 * D2; i += blockDim.x) sa[i] = a2[i];
    __syncthreads();

    int warp = tid >> 5, lane = tid & 31;
    int node = blockIdx.x * (blockDim.x >> 5) + warp;
    if (node >= NN) return;

    int beg = g_rowstart[node], end = g_rowstart[node + 1];
    float edc = g_ed1[node];

    float ax = 0.f, ay = 0.f, az = 0.f, aw = 0.f, psum = 0.f;
    for (int base = beg; base < end; base += 32) {
        int cnt = min(32, end - base);
        // all lanes: coalesced csrc load + parallel weight compute (MLP=32)
        int   s = 0;
        float w = 0.f;
        if (lane < cnt) {
            s = g_csrc[base + lane];
            w = edge_w(g_es1[s] + edc);
        }
        psum += w;
        // broadcast (s_j, w_j); row loads independent across j (high MLP)
        if (cnt == 32) {
#pragma unroll 8
            for (int j = 0; j < 32; j++) {
                int   sj = __shfl_sync(0xffffffffu, s, j);
                float wj = __shfl_sync(0xffffffffu, w, j);
                float4 v = reinterpret_cast<const float4*>(
                               g_Wh1 + (size_t)sj * D1)[lane];
                ax += wj * v.x; ay += wj * v.y; az += wj * v.z; aw += wj * v.w;
            }
        } else {
            for (int j = 0; j < cnt; j++) {
                int   sj = __shfl_sync(0xffffffffu, s, j);
                float wj = __shfl_sync(0xffffffffu, w, j);
                float4 v = reinterpret_cast<const float4*>(
                               g_Wh1 + (size_t)sj * D1)[lane];
                ax += wj * v.x; ay += wj * v.y; az += wj * v.z; aw += wj * v.w;
            }
        }
    }
    // warp-reduce the weight sum (all lanes get total)
    float asum = psum;
#pragma unroll
    for (int o = 16; o; o >>= 1) asum += __shfl_xor_sync(0xffffffffu, asum, o);

    float inv = 1.f / (asum + 1e-9f);
    ax *= inv; ay *= inv; az *= inv; aw *= inv;
    ax = (ax > 0.f) ? ax : expm1f(ax);   // elu fused
    ay = (ay > 0.f) ? ay : expm1f(ay);
    az = (az > 0.f) ? az : expm1f(az);
    aw = (aw > 0.f) ? aw : expm1f(aw);

    sh[warp][lane * 4 + 0] = ax;
    sh[warp][lane * 4 + 1] = ay;
    sh[warp][lane * 4 + 2] = az;
    sh[warp][lane * 4 + 3] = aw;
    __syncwarp();

    int j = lane;
    float acc = 0.f;
#pragma unroll 8
    for (int k = 0; k < D1; k++) acc += sh[warp][k] * sW[k * D2 + j];

    g_Wh2[(size_t)node * D2 + j] = acc;

    float es = acc * sa[j];
    float ed = acc * sa[D2 + j];
#pragma unroll
    for (int o = 16; o; o >>= 1) {
        es += __shfl_down_sync(0xffffffffu, es, o);
        ed += __shfl_down_sync(0xffffffffu, ed, o);
    }
    if (lane == 0) {
        g_es2[node] = es;
        g_ed2[node] = ed;
    }
}

// ====== fused: chunked gather layer2 (D=32) + elu + MLP head ==============
__global__ void k_gagg2_head(const float* __restrict__ hw1,
                             const float* __restrict__ hb1,
                             const float* __restrict__ hw2,
                             const float* __restrict__ hb2,
                             float* __restrict__ out) {
    __shared__ float sw1[32 * 32];
    __shared__ float sb1[32];
    __shared__ float sw2[32];
    __shared__ float sh[8][32];
    int tid = threadIdx.x;
    for (int i = tid; i < 32 * 32; i += blockDim.x) sw1[i] = hw1[i];
    if (tid < 32) { sb1[tid] = hb1[tid]; sw2[tid] = hw2[tid]; }
    __syncthreads();

    int warp = tid >> 5, lane = tid & 31;
    int node = blockIdx.x * (blockDim.x >> 5) + warp;
    if (node >= NN) return;

    int beg = g_rowstart[node], end = g_rowstart[node + 1];
    float edc = g_ed2[node];

    float acc = 0.f, psum = 0.f;
    for (int base = beg; base < end; base += 32) {
        int cnt = min(32, end - base);
        int   s = 0;
        float w = 0.f;
        if (lane < cnt) {
            s = g_csrc[base + lane];
            w = edge_w(g_es2[s] + edc);
        }
        psum += w;
        if (cnt == 32) {
#pragma unroll 8
            for (int j = 0; j < 32; j++) {
                int   sj = __shfl_sync(0xffffffffu, s, j);
                float wj = __shfl_sync(0xffffffffu, w, j);
                acc += wj * g_Wh2[(size_t)sj * D2 + lane];
            }
        } else {
            for (int j = 0; j < cnt; j++) {
                int   sj = __shfl_sync(0xffffffffu, s, j);
                float wj = __shfl_sync(0xffffffffu, w, j);
                acc += wj * g_Wh2[(size_t)sj * D2 + lane];
            }
        }
    }
    float asum = psum;
#pragma unroll
    for (int o = 16; o; o >>= 1) asum += __shfl_xor_sync(0xffffffffu, asum, o);

    acc *= 1.f / (asum + 1e-9f);
    float h = (acc > 0.f) ? acc : expm1f(acc);   // elu fused

    sh[warp][lane] = h;
    __syncwarp();

    float z = sb1[lane];
#pragma unroll 8
    for (int k = 0; k < 32; k++) z += sh[warp][k] * sw1[k * 32 + lane];

    // exact gelu: 0.5*x*(1+erf(x/sqrt(2)))
    float g = 0.5f * z * (1.f + erff(z * 0.70710678118654752f));
    float sc = g * sw2[lane];
#pragma unroll
    for (int o = 16; o; o >>= 1) sc += __shfl_down_sync(0xffffffffu, sc, o);
    if (lane == 0) out[node] = sc + hb2[0];
}

// ================= launch ==================================================
extern "C" void kernel_launch(void* const* d_in, const int* in_sizes, int n_in,
                              void* d_out, int out_size) {
    const float* x   = (const float*)d_in[0];
    const int* ei    = (const int*)d_in[1];     // int32 (JAX x64 disabled)
    const float* W1  = (const float*)d_in[2];
    const float* a1  = (const float*)d_in[3];
    const float* W2  = (const float*)d_in[4];
    const float* a2  = (const float*)d_in[5];
    const float* hw1 = (const float*)d_in[6];
    const float* hb1 = (const float*)d_in[7];
    const float* hw2 = (const float*)d_in[8];
    const float* hb2 = (const float*)d_in[9];
    float* out       = (float*)d_out;

    const int* src = ei;        // edge_index[0, :]
    const int* dst = ei + NE;   // edge_index[1, :]

    const int TB = 256;
    const int nodeBlocks = (NN + 7) / 8;        // warp per node, 8 warps/block
    const int edgeBlocks = (NE + TB - 1) / TB;
    const int zeroBlocks = (NN + TB - 1) / TB;

    // CSR build
    k_zero_deg<<<zeroBlocks, TB>>>();
    k_hist<<<edgeBlocks, TB>>>(dst);
    k_scan<<<1, 1024>>>();
    k_scatter<<<edgeBlocks, TB>>>(src, dst);

    // layer 1 + fused layer-2 projection
    k_node1<<<nodeBlocks, TB>>>(x, W1, a1);
    k_gagg1_node2<<<nodeBlocks, TB>>>(W2, a2);

    // layer 2 gather + fused head
    k_gagg2_head<<<nodeBlocks, TB>>>(hw1, hb1, hw2, hb2, out);
}